// round 15
// baseline (speedup 1.0000x reference)
#include <cuda_runtime.h>
#include <cuda_bf16.h>
#include <math.h>

#define BQ 2
#define S_LEN 2048
#define HK 16
#define HV 32
#define DK 128
#define DV 128
#define QKV 8192
#define NROWS (BQ * S_LEN)
#define TB 16   // tokens per smem staging batch (rec); 8 pairs

typedef unsigned long long ull;

// ---------------- scratch (device globals; no runtime allocation) ----------------
__device__ float g_qn[(size_t)NROWS * HK * DK];    // l2norm(q) * scale
__device__ float g_kn[(size_t)NROWS * HK * DK];    // l2norm(k)
__device__ float g_v [(size_t)NROWS * HV * DV];
__device__ float g_gate[(size_t)NROWS * HV * 2];   // float2 per (row,h): eg, beta
__device__ float2 g_cross[(size_t)BQ * (S_LEN / 2) * HK];  // per (b,tp,hk): (k1.k2, q1.k1)

// ---------------- packed f32x2 helpers ----------------
__device__ __forceinline__ ull pack2(float lo, float hi) {
    ull r;
    asm("mov.b64 %0, {%1,%2};" : "=l"(r) : "f"(lo), "f"(hi));
    return r;
}
__device__ __forceinline__ float2 unpack2(ull v) {
    float2 r;
    asm("mov.b64 {%0,%1}, %2;" : "=f"(r.x), "=f"(r.y) : "l"(v));
    return r;
}
__device__ __forceinline__ float sum2(ull v) {
    float2 r = unpack2(v);
    return r.x + r.y;
}
#define FMA2(d, a, b, c) asm("fma.rn.f32x2 %0, %1, %2, %3;" : "=l"(d) : "l"(a), "l"(b), "l"(c))
#define MUL2(d, a, b)    asm("mul.rn.f32x2 %0, %1, %2;"     : "=l"(d) : "l"(a), "l"(b))
#define ADD2(d, a, b)    asm("add.rn.f32x2 %0, %1, %2;"     : "=l"(d) : "l"(a), "l"(b))

union F4U { float4 f; ull u[2]; };

// ---------------- cp.async helpers ----------------
__device__ __forceinline__ void cpa16(void* smem, const void* gmem) {
    unsigned s = (unsigned)__cvta_generic_to_shared(smem);
    asm volatile("cp.async.cg.shared.global [%0], [%1], 16;" :: "r"(s), "l"(gmem));
}
__device__ __forceinline__ void cpa8(void* smem, const void* gmem) {
    unsigned s = (unsigned)__cvta_generic_to_shared(smem);
    asm volatile("cp.async.ca.shared.global [%0], [%1], 8;" :: "r"(s), "l"(gmem));
}
__device__ __forceinline__ void cpa_commit() {
    asm volatile("cp.async.commit_group;" ::: "memory");
}
__device__ __forceinline__ void cpa_wait0() {
    asm volatile("cp.async.wait_group 0;" ::: "memory");
}

// ---------------- kernel 1: register sliding-window conv + silu + l2norm ----------------
__global__ __launch_bounds__(256, 4) void prep_kernel(
    const float* __restrict__ x,      // [NROWS, QKV]
    const float* __restrict__ w)      // [QKV, 4]
{
    const int gw   = (blockIdx.x * 256 + threadIdx.x) >> 5;
    const int lane = threadIdx.x & 31;
    const int strip = gw & 127;
    const int hb    = (gw >> 7) & 63;
    const int b     = gw >> 13;
    const int t0    = strip * 16;
    const int ch    = hb * 128 + lane * 4;

    const float* xp = x + (size_t)(b * S_LEN + t0) * QKV + ch;

    const float4* w4 = (const float4*)w;
    const float4 wv0 = __ldg(w4 + ch + 0);
    const float4 wv1 = __ldg(w4 + ch + 1);
    const float4 wv2 = __ldg(w4 + ch + 2);
    const float4 wv3 = __ldg(w4 + ch + 3);

    float4 h0 = make_float4(0.f, 0.f, 0.f, 0.f);
    float4 h1 = h0, h2 = h0;
    if (t0 >= 3) {
        h0 = *reinterpret_cast<const float4*>(xp - 3 * QKV);
        h1 = *reinterpret_cast<const float4*>(xp - 2 * QKV);
        h2 = *reinterpret_cast<const float4*>(xp - 1 * QKV);
    }

    const float qscale = 0.08838834764831845f;

#define CONV_STEP(a, T) do {                                                        \
    const float4 xc = *reinterpret_cast<const float4*>(xp + (size_t)(T) * QKV);    \
    a.x = fmaf(h0.x, wv0.x, fmaf(h1.x, wv0.y, fmaf(h2.x, wv0.z, xc.x * wv0.w)));   \
    a.y = fmaf(h0.y, wv1.x, fmaf(h1.y, wv1.y, fmaf(h2.y, wv1.z, xc.y * wv1.w)));   \
    a.z = fmaf(h0.z, wv2.x, fmaf(h1.z, wv2.y, fmaf(h2.z, wv2.z, xc.z * wv2.w)));   \
    a.w = fmaf(h0.w, wv3.x, fmaf(h1.w, wv3.y, fmaf(h2.w, wv3.z, xc.w * wv3.w)));   \
    a.x = a.x / (1.f + __expf(-a.x));                                              \
    a.y = a.y / (1.f + __expf(-a.y));                                              \
    a.z = a.z / (1.f + __expf(-a.z));                                              \
    a.w = a.w / (1.f + __expf(-a.w));                                              \
    h0 = h1; h1 = h2; h2 = xc;                                                     \
} while (0)

    if (hb < 32) {
        const bool isq = hb < 16;
        const int head = isq ? hb : hb - 16;
        float* dbase = (isq ? g_qn : g_kn)
                     + ((size_t)(b * S_LEN + t0) * HK + head) * DK + lane * 4;
        const float sc = isq ? qscale : 1.f;
#pragma unroll
        for (int t = 0; t < 16; t++) {
            float4 a;
            CONV_STEP(a, t);
            float ss = a.x * a.x + a.y * a.y + a.z * a.z + a.w * a.w;
#pragma unroll
            for (int o = 16; o > 0; o >>= 1)
                ss += __shfl_xor_sync(0xffffffffu, ss, o);
            const float mul = rsqrtf(ss + 1e-6f) * sc;
            a.x *= mul; a.y *= mul; a.z *= mul; a.w *= mul;
            *reinterpret_cast<float4*>(dbase + (size_t)t * (HK * DK)) = a;
        }
    } else {
        const int head = hb - 32;
        float* dbase = g_v + ((size_t)(b * S_LEN + t0) * HV + head) * DV + lane * 4;
#pragma unroll
        for (int t = 0; t < 16; t++) {
            float4 a;
            CONV_STEP(a, t);
            *reinterpret_cast<float4*>(dbase + (size_t)t * (HV * DV)) = a;
        }
    }
#undef CONV_STEP
}

// ---------------- kernel 1b: gating ----------------
__global__ __launch_bounds__(256) void gate_kernel(
    const float* __restrict__ bvec,
    const float* __restrict__ avec,
    const float* __restrict__ dt_bias,
    const float* __restrict__ alog)
{
    const int idx = blockIdx.x * 256 + threadIdx.x;
    const int h = idx & 31;
    float aa = avec[idx] + __ldg(dt_bias + h);
    float sp = (aa > 20.f) ? aa : log1pf(expf(aa));
    float g  = -expf(__ldg(alog + h)) * sp;
    float eg = expf(g);
    float bb = bvec[idx];
    float beta = 1.f / (1.f + expf(-bb));
    *reinterpret_cast<float2*>(g_gate + (size_t)idx * 2) = make_float2(eg, beta);
}

// ---------------- kernel 1c: pair cross-scalars (k1.k2, q1.k1) ----------------
__global__ __launch_bounds__(256) void cross_kernel()
{
    const int gw   = blockIdx.x * 8 + (threadIdx.x >> 5);   // 32768 warps
    const int lane = threadIdx.x & 31;
    const int b  = gw >> 14;
    const int hk = (gw >> 10) & 15;
    const int tp = gw & 1023;

    const size_t base = ((size_t)(b * S_LEN + 2 * tp) * HK + hk) * DK + lane * 4;
    const float4 k1 = *reinterpret_cast<const float4*>(g_kn + base);
    const float4 k2 = *reinterpret_cast<const float4*>(g_kn + base + HK * DK);
    const float4 q1 = *reinterpret_cast<const float4*>(g_qn + base);

    float ck = k1.x * k2.x + k1.y * k2.y + k1.z * k2.z + k1.w * k2.w;
    float qk = q1.x * k1.x + q1.y * k1.y + q1.z * k1.z + q1.w * k1.w;
#pragma unroll
    for (int o = 16; o > 0; o >>= 1) {
        ck += __shfl_xor_sync(0xffffffffu, ck, o);
        qk += __shfl_xor_sync(0xffffffffu, qk, o);
    }
    if (lane == 0)
        g_cross[(size_t)(b * (S_LEN / 2) + tp) * HK + hk] = make_float2(ck, qk);
}

// ---------------- kernel 2: rank-2 gated delta-rule, 2 blocks/SM ----------------
// grid 256 = (b, h, vh, col-half). 256 threads = 32 SINGLE columns x 8 slices
// of 16 dims. Per-warp instruction structure matches the best (R12) kernel:
// 56 FMA2/pair/thread, 16 LDS.128/pair/warp (padded [8][20] conflict-free),
// 12 shfl/pair; NO owner-fold / u-exchange (each p-lane owns its full column u).
// 108 SMs host 2 independent blocks -> 4 warps/SMSP of independent streams.
__global__ __launch_bounds__(256, 2) void rec_kernel(float* __restrict__ out)
{
    const int blk = blockIdx.x;
    const int b   = blk >> 7;
    const int h   = (blk >> 2) & 31;
    const int vh  = (blk >> 1) & 1;
    const int chf = blk & 1;           // column half within vh
    const int hk  = h >> 1;

    const int tid = threadIdx.x;
    const int c   = tid >> 3;          // column 0..31
    const int p   = tid & 7;           // k-slice 0..7 (16 dims)

    __shared__ float sk[2][TB][8][20];
    __shared__ float sq[2][TB][8][20];
    __shared__ float sv[2][TB][32];
    __shared__ float2 sg[2][TB];
    __shared__ float2 scr[2][TB / 2];

    ull st[8];
#pragma unroll
    for (int i = 0; i < 8; i++) st[i] = 0ull;

    const int col0 = vh * 64 + chf * 32;
    const float* kbase = g_kn + ((size_t)(b * S_LEN) * HK + hk) * DK;
    const float* qbase = g_qn + ((size_t)(b * S_LEN) * HK + hk) * DK;
    const float* vbase = g_v  + ((size_t)(b * S_LEN) * HV + h) * DV + col0;
    const float* gbase = g_gate + ((size_t)(b * S_LEN) * HV + h) * 2;
    const size_t qk_stride = (size_t)HK * DK;
    const size_t v_stride  = (size_t)HV * DV;

    auto load_batch = [&](int buf, int t0) {
        // k and q: TB tokens x 32 float4 chunks each (512 each, 2 rounds)
#pragma unroll
        for (int rep = 0; rep < 2; rep++) {
            int i  = tid + rep * 256;
            int tt = i >> 5, j = i & 31;
            cpa16(&sk[buf][tt][j >> 2][(j & 3) * 4],
                  kbase + (size_t)(t0 + tt) * qk_stride + j * 4);
            cpa16(&sq[buf][tt][j >> 2][(j & 3) * 4],
                  qbase + (size_t)(t0 + tt) * qk_stride + j * 4);
        }
        // v: TB tokens x 8 float4 chunks = 128
        if (tid < 128) {
            int tt = tid >> 3, j = tid & 7;
            cpa16(&sv[buf][tt][j * 4],
                  vbase + (size_t)(t0 + tt) * v_stride + j * 4);
        }
        if (tid < TB)
            cpa8(&sg[buf][tid], gbase + (size_t)(t0 + tid) * (HV * 2));
        if (tid < TB / 2)
            cpa8(&scr[buf][tid],
                 &g_cross[(size_t)(b * (S_LEN / 2) + (t0 >> 1) + tid) * HK + hk]);
        cpa_commit();
    };

    load_batch(0, 0);
    cpa_wait0();
    __syncthreads();
    int buf = 0;

    float* obase = out + ((size_t)(b * S_LEN) * HV + h) * DV + col0 + c;

    float oo = 0.f;                    // prev token's o2 partial (this column)

#pragma unroll 1
    for (int t0 = 0; t0 < S_LEN; t0 += TB) {
        if (t0 + TB < S_LEN) load_batch(buf ^ 1, t0 + TB);

#pragma unroll 2
        for (int pp = 0; pp < TB / 2; pp++) {
            const int T = t0 + 2 * pp;
            const int s1 = 2 * pp, s2 = 2 * pp + 1;

            const float2 ga = sg[buf][s1];
            const float2 gb = sg[buf][s2];
            const float e1 = ga.x, b1 = ga.y, e2 = gb.x, b2 = gb.y;
            const float2 cr = scr[buf][pp];

            // slices: 16 floats = 4 float4 each (k1, k2 live through update)
            F4U k1[4], k2[4];
            {
                const float* k1p = &sk[buf][s1][p][0];
                const float* k2p = &sk[buf][s2][p][0];
#pragma unroll
                for (int i = 0; i < 4; i++) {
                    k1[i].f = *reinterpret_cast<const float4*>(k1p + i * 4);
                    k2[i].f = *reinterpret_cast<const float4*>(k2p + i * 4);
                }
            }
            // dots on pre-update state: Pa = k1.S, Pb = k2.S, G1 = q1.S
            ull A = 0, B = 0, C = 0;
            {
                F4U q1[4];
                const float* q1p = &sq[buf][s1][p][0];
#pragma unroll
                for (int i = 0; i < 4; i++)
                    q1[i].f = *reinterpret_cast<const float4*>(q1p + i * 4);
#pragma unroll
                for (int i = 0; i < 4; i++) {
                    FMA2(A, k1[i].u[0], st[2*i],   A);
                    FMA2(A, k1[i].u[1], st[2*i+1], A);
                    FMA2(B, k2[i].u[0], st[2*i],   B);
                    FMA2(B, k2[i].u[1], st[2*i+1], B);
                    FMA2(C, q1[i].u[0], st[2*i],   C);
                    FMA2(C, q1[i].u[1], st[2*i+1], C);
                }
            }
            float Pa = sum2(A), Pb = sum2(B), G1 = sum2(C);

            // ONE interleaved burst: 4 chains x tree(1,2,4) over the 8 p-lanes
#pragma unroll
            for (int o = 1; o <= 4; o <<= 1) {
                Pa += __shfl_xor_sync(0xffffffffu, Pa, o);
                Pb += __shfl_xor_sync(0xffffffffu, Pb, o);
                G1 += __shfl_xor_sync(0xffffffffu, G1, o);
                oo += __shfl_xor_sync(0xffffffffu, oo, o);
            }

            // prev token's o2 store (deferred)
            if (T != 0 && p == 0)
                obase[(size_t)(T - 1) * v_stride] = oo;

            // scalar chain (all 8 p-lanes redundantly compute the column's u's)
            const float v1 = sv[buf][s1][c];
            const float v2 = sv[buf][s2][c];
            const float u1 = b1 * (v1 - e1 * Pa);
            const float k2S1 = e1 * Pb + cr.x * u1;
            const float u2 = b2 * (v2 - e2 * k2S1);
            const float o1 = e1 * G1 + cr.y * u1;
            if (p == 0)
                obase[(size_t)T * v_stride] = o1;

            // state update: S2 = e12*S0 + (e2*u1)*k1 + u2*k2  (no exchange!)
            const float e12 = e1 * e2;
            const float c1 = e2 * u1;
            const ull ep  = pack2(e12, e12);
            const ull c1p = pack2(c1, c1), u2p = pack2(u2, u2);
#pragma unroll
            for (int i = 0; i < 4; i++) {
                MUL2(st[2*i],   st[2*i],   ep);
                MUL2(st[2*i+1], st[2*i+1], ep);
                FMA2(st[2*i],   k1[i].u[0], c1p, st[2*i]);
                FMA2(st[2*i+1], k1[i].u[1], c1p, st[2*i+1]);
                FMA2(st[2*i],   k2[i].u[0], u2p, st[2*i]);
                FMA2(st[2*i+1], k2[i].u[1], u2p, st[2*i+1]);
            }

            // deferred o2 partial: q2 . S2 (reduced next iteration)
            {
                F4U q2[4];
                const float* q2p = &sq[buf][s2][p][0];
#pragma unroll
                for (int i = 0; i < 4; i++)
                    q2[i].f = *reinterpret_cast<const float4*>(q2p + i * 4);
                ull Q = 0;
#pragma unroll
                for (int i = 0; i < 4; i++) {
                    FMA2(Q, q2[i].u[0], st[2*i],   Q);
                    FMA2(Q, q2[i].u[1], st[2*i+1], Q);
                }
                oo = sum2(Q);
            }
        }

        cpa_wait0();
        __syncthreads();
        buf ^= 1;
    }

    // drain: reduce and store the final token's o2
    {
#pragma unroll
        for (int o = 1; o <= 4; o <<= 1)
            oo += __shfl_xor_sync(0xffffffffu, oo, o);
        if (p == 0)
            obase[(size_t)(S_LEN - 1) * v_stride] = oo;
    }
}

// ---------------- launch ----------------
extern "C" void kernel_launch(void* const* d_in, const int* in_sizes, int n_in,
                              void* d_out, int out_size)
{
    const float* mixed_qkv = (const float*)d_in[0];
    const float* bvec      = (const float*)d_in[1];
    const float* avec      = (const float*)d_in[2];
    const float* convw     = (const float*)d_in[3];
    const float* dt_bias   = (const float*)d_in[4];
    const float* alog      = (const float*)d_in[5];
    float* out = (float*)d_out;

    prep_kernel<<<2048, 256>>>(mixed_qkv, convw);
    cross_kernel<<<BQ * HK * (S_LEN / 2) / 8, 256>>>();
    gate_kernel<<<NROWS * HV / 256, 256>>>(bvec, avec, dt_bias, alog);
    rec_kernel<<<BQ * HV * 2 * 2, 256>>>(out);
}

// round 16
// speedup vs baseline: 1.4069x; 1.4069x over previous
#include <cuda_runtime.h>
#include <cuda_bf16.h>
#include <math.h>

#define BQ 2
#define S_LEN 2048
#define HK 16
#define HV 32
#define DK 128
#define DV 128
#define QKV 8192
#define NROWS (BQ * S_LEN)
#define TB 16   // tokens per smem staging batch (rec); 8 pairs

typedef unsigned long long ull;

// ---------------- scratch (device globals; no runtime allocation) ----------------
__device__ float g_qn[(size_t)NROWS * HK * DK];    // l2norm(q) * scale
__device__ float g_kn[(size_t)NROWS * HK * DK];    // l2norm(k)
__device__ float g_v [(size_t)NROWS * HV * DV];
__device__ float g_gate[(size_t)NROWS * HV * 2];   // float2 per (row,h): eg, beta
// per (b, pair, hk): (k1.k2, q1.k1, q2.k1, q2.k2)
__device__ float4 g_cross[(size_t)BQ * (S_LEN / 2) * HK];

// ---------------- packed f32x2 helpers ----------------
__device__ __forceinline__ ull pack2(float lo, float hi) {
    ull r;
    asm("mov.b64 %0, {%1,%2};" : "=l"(r) : "f"(lo), "f"(hi));
    return r;
}
__device__ __forceinline__ float2 unpack2(ull v) {
    float2 r;
    asm("mov.b64 {%0,%1}, %2;" : "=f"(r.x), "=f"(r.y) : "l"(v));
    return r;
}
__device__ __forceinline__ float sum2(ull v) {
    float2 r = unpack2(v);
    return r.x + r.y;
}
#define FMA2(d, a, b, c) asm("fma.rn.f32x2 %0, %1, %2, %3;" : "=l"(d) : "l"(a), "l"(b), "l"(c))
#define MUL2(d, a, b)    asm("mul.rn.f32x2 %0, %1, %2;"     : "=l"(d) : "l"(a), "l"(b))
#define ADD2(d, a, b)    asm("add.rn.f32x2 %0, %1, %2;"     : "=l"(d) : "l"(a), "l"(b))

union F4U { float4 f; ull u[2]; };

// ---------------- cp.async helpers ----------------
__device__ __forceinline__ void cpa16(void* smem, const void* gmem) {
    unsigned s = (unsigned)__cvta_generic_to_shared(smem);
    asm volatile("cp.async.cg.shared.global [%0], [%1], 16;" :: "r"(s), "l"(gmem));
}
__device__ __forceinline__ void cpa8(void* smem, const void* gmem) {
    unsigned s = (unsigned)__cvta_generic_to_shared(smem);
    asm volatile("cp.async.ca.shared.global [%0], [%1], 8;" :: "r"(s), "l"(gmem));
}
__device__ __forceinline__ void cpa_commit() {
    asm volatile("cp.async.commit_group;" ::: "memory");
}
__device__ __forceinline__ void cpa_wait0() {
    asm volatile("cp.async.wait_group 0;" ::: "memory");
}

// ---------------- kernel 1: register sliding-window conv + silu + l2norm ----------------
__global__ __launch_bounds__(256, 4) void prep_kernel(
    const float* __restrict__ x,      // [NROWS, QKV]
    const float* __restrict__ w)      // [QKV, 4]
{
    const int gw   = (blockIdx.x * 256 + threadIdx.x) >> 5;
    const int lane = threadIdx.x & 31;
    const int strip = gw & 127;
    const int hb    = (gw >> 7) & 63;
    const int b     = gw >> 13;
    const int t0    = strip * 16;
    const int ch    = hb * 128 + lane * 4;

    const float* xp = x + (size_t)(b * S_LEN + t0) * QKV + ch;

    const float4* w4 = (const float4*)w;
    const float4 wv0 = __ldg(w4 + ch + 0);
    const float4 wv1 = __ldg(w4 + ch + 1);
    const float4 wv2 = __ldg(w4 + ch + 2);
    const float4 wv3 = __ldg(w4 + ch + 3);

    float4 h0 = make_float4(0.f, 0.f, 0.f, 0.f);
    float4 h1 = h0, h2 = h0;
    if (t0 >= 3) {
        h0 = *reinterpret_cast<const float4*>(xp - 3 * QKV);
        h1 = *reinterpret_cast<const float4*>(xp - 2 * QKV);
        h2 = *reinterpret_cast<const float4*>(xp - 1 * QKV);
    }

    const float qscale = 0.08838834764831845f;

#define CONV_STEP(a, T) do {                                                        \
    const float4 xc = *reinterpret_cast<const float4*>(xp + (size_t)(T) * QKV);    \
    a.x = fmaf(h0.x, wv0.x, fmaf(h1.x, wv0.y, fmaf(h2.x, wv0.z, xc.x * wv0.w)));   \
    a.y = fmaf(h0.y, wv1.x, fmaf(h1.y, wv1.y, fmaf(h2.y, wv1.z, xc.y * wv1.w)));   \
    a.z = fmaf(h0.z, wv2.x, fmaf(h1.z, wv2.y, fmaf(h2.z, wv2.z, xc.z * wv2.w)));   \
    a.w = fmaf(h0.w, wv3.x, fmaf(h1.w, wv3.y, fmaf(h2.w, wv3.z, xc.w * wv3.w)));   \
    a.x = a.x / (1.f + __expf(-a.x));                                              \
    a.y = a.y / (1.f + __expf(-a.y));                                              \
    a.z = a.z / (1.f + __expf(-a.z));                                              \
    a.w = a.w / (1.f + __expf(-a.w));                                              \
    h0 = h1; h1 = h2; h2 = xc;                                                     \
} while (0)

    if (hb < 32) {
        const bool isq = hb < 16;
        const int head = isq ? hb : hb - 16;
        float* dbase = (isq ? g_qn : g_kn)
                     + ((size_t)(b * S_LEN + t0) * HK + head) * DK + lane * 4;
        const float sc = isq ? qscale : 1.f;
#pragma unroll
        for (int t = 0; t < 16; t++) {
            float4 a;
            CONV_STEP(a, t);
            float ss = a.x * a.x + a.y * a.y + a.z * a.z + a.w * a.w;
#pragma unroll
            for (int o = 16; o > 0; o >>= 1)
                ss += __shfl_xor_sync(0xffffffffu, ss, o);
            const float mul = rsqrtf(ss + 1e-6f) * sc;
            a.x *= mul; a.y *= mul; a.z *= mul; a.w *= mul;
            *reinterpret_cast<float4*>(dbase + (size_t)t * (HK * DK)) = a;
        }
    } else {
        const int head = hb - 32;
        float* dbase = g_v + ((size_t)(b * S_LEN + t0) * HV + head) * DV + lane * 4;
#pragma unroll
        for (int t = 0; t < 16; t++) {
            float4 a;
            CONV_STEP(a, t);
            *reinterpret_cast<float4*>(dbase + (size_t)t * (HV * DV)) = a;
        }
    }
#undef CONV_STEP
}

// ---------------- kernel 1b: gating ----------------
__global__ __launch_bounds__(256) void gate_kernel(
    const float* __restrict__ bvec,
    const float* __restrict__ avec,
    const float* __restrict__ dt_bias,
    const float* __restrict__ alog)
{
    const int idx = blockIdx.x * 256 + threadIdx.x;
    const int h = idx & 31;
    float aa = avec[idx] + __ldg(dt_bias + h);
    float sp = (aa > 20.f) ? aa : log1pf(expf(aa));
    float g  = -expf(__ldg(alog + h)) * sp;
    float eg = expf(g);
    float bb = bvec[idx];
    float beta = 1.f / (1.f + expf(-bb));
    *reinterpret_cast<float2*>(g_gate + (size_t)idx * 2) = make_float2(eg, beta);
}

// ---------------- kernel 1c: pair cross-scalars ----------------
// One warp per (b, hk, pair): (k1.k2, q1.k1, q2.k1, q2.k2)
__global__ __launch_bounds__(256) void cross_kernel()
{
    const int gw   = blockIdx.x * 8 + (threadIdx.x >> 5);   // 32768 warps
    const int lane = threadIdx.x & 31;
    const int b  = gw >> 14;
    const int hk = (gw >> 10) & 15;
    const int tp = gw & 1023;

    const size_t base = ((size_t)(b * S_LEN + 2 * tp) * HK + hk) * DK + lane * 4;
    const float4 k1 = *reinterpret_cast<const float4*>(g_kn + base);
    const float4 k2 = *reinterpret_cast<const float4*>(g_kn + base + HK * DK);
    const float4 q1 = *reinterpret_cast<const float4*>(g_qn + base);
    const float4 q2 = *reinterpret_cast<const float4*>(g_qn + base + HK * DK);

    float ck   = k1.x * k2.x + k1.y * k2.y + k1.z * k2.z + k1.w * k2.w;
    float qk11 = q1.x * k1.x + q1.y * k1.y + q1.z * k1.z + q1.w * k1.w;
    float qk21 = q2.x * k1.x + q2.y * k1.y + q2.z * k1.z + q2.w * k1.w;
    float qk22 = q2.x * k2.x + q2.y * k2.y + q2.z * k2.z + q2.w * k2.w;
#pragma unroll
    for (int o = 16; o > 0; o >>= 1) {
        ck   += __shfl_xor_sync(0xffffffffu, ck,   o);
        qk11 += __shfl_xor_sync(0xffffffffu, qk11, o);
        qk21 += __shfl_xor_sync(0xffffffffu, qk21, o);
        qk22 += __shfl_xor_sync(0xffffffffu, qk22, o);
    }
    if (lane == 0)
        g_cross[(size_t)(b * (S_LEN / 2) + tp) * HK + hk] =
            make_float4(ck, qk11, qk21, qk22);
}

// ---------------- kernel 2: rank-2 gated delta-rule (all dots on S0) ----------------
// grid 128 = (b, h, vh). 256 threads = 32 column-pairs x 8 k-slices of 16 dims.
// Per pair: FOUR dots on the old state (k1,k2,q1,q2) x (own,other col) at the
// loop head (max ILP), one interleaved 12-shfl burst, then ALL outputs computed
// from scalars: o1 = e1*G1 + (q1.k1)u1; o2 = e12*G2 + e2*(q2.k1)u1 + (q2.k2)u2.
// No deferred dot, no cross-iteration carry. Update = last op before next pair.
__global__ __launch_bounds__(256, 1) void rec_kernel(float* __restrict__ out)
{
    const int blk = blockIdx.x;
    const int b   = blk >> 6;
    const int h   = (blk >> 1) & 31;
    const int vh  = blk & 1;
    const int hk  = h >> 1;

    const int tid = threadIdx.x;
    const int c2  = tid >> 3;          // column pair 0..31
    const int p   = tid & 7;           // k-slice 0..7 (16 dims)
    const bool lowp = (p < 4);

    __shared__ float sk[2][TB][8][20];
    __shared__ float sq[2][TB][8][20];
    __shared__ float sv[2][TB][64];
    __shared__ float2 sg[2][TB];
    __shared__ float4 scr[2][TB / 2];

    ull so[8], sx[8];                  // owned / other column state
#pragma unroll
    for (int i = 0; i < 8; i++) { so[i] = 0ull; sx[i] = 0ull; }

    const float* kbase = g_kn + ((size_t)(b * S_LEN) * HK + hk) * DK;
    const float* qbase = g_qn + ((size_t)(b * S_LEN) * HK + hk) * DK;
    const float* vbase = g_v  + ((size_t)(b * S_LEN) * HV + h) * DV + vh * 64;
    const float* gbase = g_gate + ((size_t)(b * S_LEN) * HV + h) * 2;
    const size_t qk_stride = (size_t)HK * DK;
    const size_t v_stride  = (size_t)HV * DV;

    auto load_batch = [&](int buf, int t0) {
#pragma unroll
        for (int rep = 0; rep < 2; rep++) {
            int i  = tid + rep * 256;
            int tt = i >> 5, j = i & 31;
            cpa16(&sk[buf][tt][j >> 2][(j & 3) * 4],
                  kbase + (size_t)(t0 + tt) * qk_stride + j * 4);
            cpa16(&sq[buf][tt][j >> 2][(j & 3) * 4],
                  qbase + (size_t)(t0 + tt) * qk_stride + j * 4);
        }
        {
            int tt = tid >> 4, j = tid & 15;
            cpa16(&sv[buf][tt][j * 4],
                  vbase + (size_t)(t0 + tt) * v_stride + j * 4);
        }
        if (tid < TB)
            cpa8(&sg[buf][tid], gbase + (size_t)(t0 + tid) * (HV * 2));
        if (tid < TB / 2)
            cpa16(&scr[buf][tid],
                  &g_cross[(size_t)(b * (S_LEN / 2) + (t0 >> 1) + tid) * HK + hk]);
        cpa_commit();
    };

    load_batch(0, 0);
    cpa_wait0();
    __syncthreads();
    int buf = 0;

    float* obase = out + ((size_t)(b * S_LEN) * HV + h) * DV + vh * 64 + c2 * 2;
    const int osel = lowp ? 0 : 1;

    F4U k1A[4], k2A[4], q1A[4], q2A[4];
    F4U k1B[4], k2B[4], q1B[4], q2B[4];

#define PLOAD(k1r, k2r, q1r, q2r, PP) do {                                    \
    const int _s = (PP) * 2;                                                  \
    const float* _k1 = &sk[buf][_s][p][0];                                    \
    const float* _k2 = &sk[buf][_s + 1][p][0];                                \
    const float* _q1 = &sq[buf][_s][p][0];                                    \
    const float* _q2 = &sq[buf][_s + 1][p][0];                                \
    _Pragma("unroll")                                                         \
    for (int i = 0; i < 4; i++) {                                             \
        k1r[i].f = *reinterpret_cast<const float4*>(_k1 + i * 4);             \
        k2r[i].f = *reinterpret_cast<const float4*>(_k2 + i * 4);             \
        q1r[i].f = *reinterpret_cast<const float4*>(_q1 + i * 4);             \
        q2r[i].f = *reinterpret_cast<const float4*>(_q2 + i * 4);             \
    }                                                                         \
} while (0)

#define PBODY(k1r, k2r, q1r, q2r, PP, T) do {                                 \
    const float2 ga = sg[buf][2 * (PP)];                                      \
    const float2 gb = sg[buf][2 * (PP) + 1];                                  \
    const float e1 = ga.x, b1 = ga.y, e2 = gb.x, b2 = gb.y;                   \
    const float4 cr = scr[buf][PP];                                           \
    ull A = 0, B = 0, C = 0, G = 0, D = 0, E = 0, F = 0, H = 0;               \
    _Pragma("unroll")                                                         \
    for (int i = 0; i < 4; i++) {                                             \
        FMA2(A, k1r[i].u[0], so[2*i],   A);                                   \
        FMA2(A, k1r[i].u[1], so[2*i+1], A);                                   \
        FMA2(B, k2r[i].u[0], so[2*i],   B);                                   \
        FMA2(B, k2r[i].u[1], so[2*i+1], B);                                   \
        FMA2(C, q1r[i].u[0], so[2*i],   C);                                   \
        FMA2(C, q1r[i].u[1], so[2*i+1], C);                                   \
        FMA2(G, q2r[i].u[0], so[2*i],   G);                                   \
        FMA2(G, q2r[i].u[1], so[2*i+1], G);                                   \
        FMA2(D, k1r[i].u[0], sx[2*i],   D);                                   \
        FMA2(D, k1r[i].u[1], sx[2*i+1], D);                                   \
        FMA2(E, k2r[i].u[0], sx[2*i],   E);                                   \
        FMA2(E, k2r[i].u[1], sx[2*i+1], E);                                   \
        FMA2(F, q1r[i].u[0], sx[2*i],   F);                                   \
        FMA2(F, q1r[i].u[1], sx[2*i+1], F);                                   \
        FMA2(H, q2r[i].u[0], sx[2*i],   H);                                   \
        FMA2(H, q2r[i].u[1], sx[2*i+1], H);                                   \
    }                                                                         \
    float Pam = sum2(A), Pbm = sum2(B), G1m = sum2(C), G2m = sum2(G);         \
    const float PaO = sum2(D), PbO = sum2(E), G1O = sum2(F), G2O = sum2(H);   \
    Pam += __shfl_xor_sync(0xffffffffu, PaO, 4);                              \
    Pbm += __shfl_xor_sync(0xffffffffu, PbO, 4);                              \
    G1m += __shfl_xor_sync(0xffffffffu, G1O, 4);                              \
    G2m += __shfl_xor_sync(0xffffffffu, G2O, 4);                              \
    Pam += __shfl_xor_sync(0xffffffffu, Pam, 1);                              \
    Pbm += __shfl_xor_sync(0xffffffffu, Pbm, 1);                              \
    G1m += __shfl_xor_sync(0xffffffffu, G1m, 1);                              \
    G2m += __shfl_xor_sync(0xffffffffu, G2m, 1);                              \
    Pam += __shfl_xor_sync(0xffffffffu, Pam, 2);                              \
    Pbm += __shfl_xor_sync(0xffffffffu, Pbm, 2);                              \
    G1m += __shfl_xor_sync(0xffffffffu, G1m, 2);                              \
    G2m += __shfl_xor_sync(0xffffffffu, G2m, 2);                              \
    const float2 v1f = *reinterpret_cast<const float2*>(&sv[buf][2*(PP)][c2*2]);   \
    const float2 v2f = *reinterpret_cast<const float2*>(&sv[buf][2*(PP)+1][c2*2]); \
    const float v1o = lowp ? v1f.x : v1f.y;                                   \
    const float v2o = lowp ? v2f.x : v2f.y;                                   \
    const float u1 = b1 * (v1o - e1 * Pam);                                   \
    const float k2S1 = e1 * Pbm + cr.x * u1;                                  \
    const float u2 = b2 * (v2o - e2 * k2S1);                                  \
    const float e12 = e1 * e2;                                                \
    const float o1 = e1 * G1m + cr.y * u1;                                    \
    const float o2 = e12 * G2m + e2 * cr.z * u1 + cr.w * u2;                  \
    if ((p & 3) == 0) {                                                       \
        obase[(size_t)(T) * v_stride + osel]     = o1;                        \
        obase[(size_t)(T + 1) * v_stride + osel] = o2;                        \
    }                                                                         \
    const float c1 = e2 * u1;                                                 \
    const float c1x = __shfl_xor_sync(0xffffffffu, c1, 4);                    \
    const float u2x = __shfl_xor_sync(0xffffffffu, u2, 4);                    \
    const ull ep  = pack2(e12, e12);                                          \
    const ull c1p = pack2(c1, c1), u2p = pack2(u2, u2);                       \
    _Pragma("unroll")                                                         \
    for (int i = 0; i < 8; i++) {        /* owned update overlaps exchange */ \
        MUL2(so[i], so[i], ep);                                               \
    }                                                                         \
    _Pragma("unroll")                                                         \
    for (int i = 0; i < 4; i++) {                                             \
        FMA2(so[2*i],   k1r[i].u[0], c1p, so[2*i]);                           \
        FMA2(so[2*i+1], k1r[i].u[1], c1p, so[2*i+1]);                         \
        FMA2(so[2*i],   k2r[i].u[0], u2p, so[2*i]);                           \
        FMA2(so[2*i+1], k2r[i].u[1], u2p, so[2*i+1]);                         \
    }                                                                         \
    const ull c1xp = pack2(c1x, c1x), u2xp = pack2(u2x, u2x);                 \
    _Pragma("unroll")                                                         \
    for (int i = 0; i < 4; i++) {                                             \
        MUL2(sx[2*i],   sx[2*i],   ep);                                       \
        MUL2(sx[2*i+1], sx[2*i+1], ep);                                       \
        FMA2(sx[2*i],   k1r[i].u[0], c1xp, sx[2*i]);                          \
        FMA2(sx[2*i+1], k1r[i].u[1], c1xp, sx[2*i+1]);                        \
        FMA2(sx[2*i],   k2r[i].u[0], u2xp, sx[2*i]);                          \
        FMA2(sx[2*i+1], k2r[i].u[1], u2xp, sx[2*i+1]);                        \
    }                                                                         \
} while (0)

#pragma unroll 1
    for (int t0 = 0; t0 < S_LEN; t0 += TB) {
        if (t0 + TB < S_LEN) load_batch(buf ^ 1, t0 + TB);

        PLOAD(k1A, k2A, q1A, q2A, 0);
#pragma unroll 2
        for (int pp = 0; pp < TB / 2; pp += 2) {
            PLOAD(k1B, k2B, q1B, q2B, pp + 1);
            PBODY(k1A, k2A, q1A, q2A, pp, t0 + 2 * pp);
            {
                int pn = pp + 2; if (pn > TB / 2 - 1) pn = TB / 2 - 1;
                PLOAD(k1A, k2A, q1A, q2A, pn);
            }
            PBODY(k1B, k2B, q1B, q2B, pp + 1, t0 + 2 * (pp + 1));
        }

        cpa_wait0();
        __syncthreads();
        buf ^= 1;
    }
#undef PLOAD
#undef PBODY
}

// ---------------- launch ----------------
extern "C" void kernel_launch(void* const* d_in, const int* in_sizes, int n_in,
                              void* d_out, int out_size)
{
    const float* mixed_qkv = (const float*)d_in[0];
    const float* bvec      = (const float*)d_in[1];
    const float* avec      = (const float*)d_in[2];
    const float* convw     = (const float*)d_in[3];
    const float* dt_bias   = (const float*)d_in[4];
    const float* alog      = (const float*)d_in[5];
    float* out = (float*)d_out;

    prep_kernel<<<2048, 256>>>(mixed_qkv, convw);
    cross_kernel<<<BQ * HK * (S_LEN / 2) / 8, 256>>>();
    gate_kernel<<<NROWS * HV / 256, 256>>>(bvec, avec, dt_bias, alog);
    rec_kernel<<<BQ * HV * 2, 256>>>(out);
}

// round 17
// speedup vs baseline: 1.5835x; 1.1255x over previous
#include <cuda_runtime.h>
#include <cuda_bf16.h>
#include <math.h>

#define BQ 2
#define S_LEN 2048
#define HK 16
#define HV 32
#define DK 128
#define DV 128
#define QKV 8192
#define NROWS (BQ * S_LEN)
#define TB 8    // tokens per smem staging batch per group (rec); 4 pairs

typedef unsigned long long ull;

// ---------------- scratch (device globals; no runtime allocation) ----------------
__device__ float g_qn[(size_t)NROWS * HK * DK];    // l2norm(q) * scale
__device__ float g_kn[(size_t)NROWS * HK * DK];    // l2norm(k)
__device__ float g_v [(size_t)NROWS * HV * DV];
__device__ float g_gate[(size_t)NROWS * HV * 2];   // float2 per (row,h): eg, beta
__device__ float2 g_cross[(size_t)BQ * (S_LEN / 2) * HK];  // per (b,tp,hk): (k1.k2, q1.k1)

// ---------------- packed f32x2 helpers ----------------
__device__ __forceinline__ ull pack2(float lo, float hi) {
    ull r;
    asm("mov.b64 %0, {%1,%2};" : "=l"(r) : "f"(lo), "f"(hi));
    return r;
}
__device__ __forceinline__ float2 unpack2(ull v) {
    float2 r;
    asm("mov.b64 {%0,%1}, %2;" : "=f"(r.x), "=f"(r.y) : "l"(v));
    return r;
}
__device__ __forceinline__ float sum2(ull v) {
    float2 r = unpack2(v);
    return r.x + r.y;
}
#define FMA2(d, a, b, c) asm("fma.rn.f32x2 %0, %1, %2, %3;" : "=l"(d) : "l"(a), "l"(b), "l"(c))
#define MUL2(d, a, b)    asm("mul.rn.f32x2 %0, %1, %2;"     : "=l"(d) : "l"(a), "l"(b))
#define ADD2(d, a, b)    asm("add.rn.f32x2 %0, %1, %2;"     : "=l"(d) : "l"(a), "l"(b))

union F4U { float4 f; ull u[2]; };

// ---------------- cp.async helpers ----------------
__device__ __forceinline__ void cpa16(void* smem, const void* gmem) {
    unsigned s = (unsigned)__cvta_generic_to_shared(smem);
    asm volatile("cp.async.cg.shared.global [%0], [%1], 16;" :: "r"(s), "l"(gmem));
}
__device__ __forceinline__ void cpa8(void* smem, const void* gmem) {
    unsigned s = (unsigned)__cvta_generic_to_shared(smem);
    asm volatile("cp.async.ca.shared.global [%0], [%1], 8;" :: "r"(s), "l"(gmem));
}
__device__ __forceinline__ void cpa_commit() {
    asm volatile("cp.async.commit_group;" ::: "memory");
}
__device__ __forceinline__ void cpa_wait0() {
    asm volatile("cp.async.wait_group 0;" ::: "memory");
}

// ---------------- kernel 1: register sliding-window conv + silu + l2norm ----------------
__global__ __launch_bounds__(256) void prep_kernel(
    const float* __restrict__ x,      // [NROWS, QKV]
    const float* __restrict__ w)      // [QKV, 4]
{
    const int gw   = (blockIdx.x * 256 + threadIdx.x) >> 5;
    const int lane = threadIdx.x & 31;
    const int strip = gw & 127;
    const int hb    = (gw >> 7) & 63;
    const int b     = gw >> 13;
    const int t0    = strip * 16;
    const int ch    = hb * 128 + lane * 4;

    const float* xp = x + (size_t)(b * S_LEN + t0) * QKV + ch;

    const float4* w4 = (const float4*)w;
    const float4 wv0 = __ldg(w4 + ch + 0);
    const float4 wv1 = __ldg(w4 + ch + 1);
    const float4 wv2 = __ldg(w4 + ch + 2);
    const float4 wv3 = __ldg(w4 + ch + 3);

    float4 h0 = make_float4(0.f, 0.f, 0.f, 0.f);
    float4 h1 = h0, h2 = h0;
    if (t0 >= 3) {
        h0 = *reinterpret_cast<const float4*>(xp - 3 * QKV);
        h1 = *reinterpret_cast<const float4*>(xp - 2 * QKV);
        h2 = *reinterpret_cast<const float4*>(xp - 1 * QKV);
    }

    const float qscale = 0.08838834764831845f;

#define CONV_STEP(a, T) do {                                                        \
    const float4 xc = *reinterpret_cast<const float4*>(xp + (size_t)(T) * QKV);    \
    a.x = fmaf(h0.x, wv0.x, fmaf(h1.x, wv0.y, fmaf(h2.x, wv0.z, xc.x * wv0.w)));   \
    a.y = fmaf(h0.y, wv1.x, fmaf(h1.y, wv1.y, fmaf(h2.y, wv1.z, xc.y * wv1.w)));   \
    a.z = fmaf(h0.z, wv2.x, fmaf(h1.z, wv2.y, fmaf(h2.z, wv2.z, xc.z * wv2.w)));   \
    a.w = fmaf(h0.w, wv3.x, fmaf(h1.w, wv3.y, fmaf(h2.w, wv3.z, xc.w * wv3.w)));   \
    a.x = a.x / (1.f + __expf(-a.x));                                              \
    a.y = a.y / (1.f + __expf(-a.y));                                              \
    a.z = a.z / (1.f + __expf(-a.z));                                              \
    a.w = a.w / (1.f + __expf(-a.w));                                              \
    h0 = h1; h1 = h2; h2 = xc;                                                     \
} while (0)

    if (hb < 32) {
        const bool isq = hb < 16;
        const int head = isq ? hb : hb - 16;
        float* dbase = (isq ? g_qn : g_kn)
                     + ((size_t)(b * S_LEN + t0) * HK + head) * DK + lane * 4;
        const float sc = isq ? qscale : 1.f;
#pragma unroll
        for (int t = 0; t < 16; t++) {
            float4 a;
            CONV_STEP(a, t);
            float ss = a.x * a.x + a.y * a.y + a.z * a.z + a.w * a.w;
#pragma unroll
            for (int o = 16; o > 0; o >>= 1)
                ss += __shfl_xor_sync(0xffffffffu, ss, o);
            const float mul = rsqrtf(ss + 1e-6f) * sc;
            a.x *= mul; a.y *= mul; a.z *= mul; a.w *= mul;
            *reinterpret_cast<float4*>(dbase + (size_t)t * (HK * DK)) = a;
        }
    } else {
        const int head = hb - 32;
        float* dbase = g_v + ((size_t)(b * S_LEN + t0) * HV + head) * DV + lane * 4;
#pragma unroll
        for (int t = 0; t < 16; t++) {
            float4 a;
            CONV_STEP(a, t);
            *reinterpret_cast<float4*>(dbase + (size_t)t * (HV * DV)) = a;
        }
    }
#undef CONV_STEP
}

// ---------------- kernel 1b: gating ----------------
__global__ __launch_bounds__(256) void gate_kernel(
    const float* __restrict__ bvec,
    const float* __restrict__ avec,
    const float* __restrict__ dt_bias,
    const float* __restrict__ alog)
{
    const int idx = blockIdx.x * 256 + threadIdx.x;
    const int h = idx & 31;
    float aa = avec[idx] + __ldg(dt_bias + h);
    float sp = (aa > 20.f) ? aa : log1pf(expf(aa));
    float g  = -expf(__ldg(alog + h)) * sp;
    float eg = expf(g);
    float bb = bvec[idx];
    float beta = 1.f / (1.f + expf(-bb));
    *reinterpret_cast<float2*>(g_gate + (size_t)idx * 2) = make_float2(eg, beta);
}

// ---------------- kernel 1c: pair cross-scalars (k1.k2, q1.k1) ----------------
__global__ __launch_bounds__(256) void cross_kernel()
{
    const int gw   = blockIdx.x * 8 + (threadIdx.x >> 5);   // 32768 warps
    const int lane = threadIdx.x & 31;
    const int b  = gw >> 14;
    const int hk = (gw >> 10) & 15;
    const int tp = gw & 1023;

    const size_t base = ((size_t)(b * S_LEN + 2 * tp) * HK + hk) * DK + lane * 4;
    const float4 k1 = *reinterpret_cast<const float4*>(g_kn + base);
    const float4 k2 = *reinterpret_cast<const float4*>(g_kn + base + HK * DK);
    const float4 q1 = *reinterpret_cast<const float4*>(g_qn + base);

    float ck = k1.x * k2.x + k1.y * k2.y + k1.z * k2.z + k1.w * k2.w;
    float qk = q1.x * k1.x + q1.y * k1.y + q1.z * k1.z + q1.w * k1.w;
#pragma unroll
    for (int o = 16; o > 0; o >>= 1) {
        ck += __shfl_xor_sync(0xffffffffu, ck, o);
        qk += __shfl_xor_sync(0xffffffffu, qk, o);
    }
    if (lane == 0)
        g_cross[(size_t)(b * (S_LEN / 2) + tp) * HK + hk] = make_float2(ck, qk);
}

// ---------------- kernel 2: rank-2 gated delta-rule, TWO phase-independent groups ----------------
// grid 128 = (b, h, vh). 256 threads = 2 groups x (16 column-pairs x 8 k-slices).
// Group g owns columns vh*64 + g*32 .. +32, its OWN k/q/v staging buffers and
// its own named barrier (bar.sync g+1, 128). Per-warp instruction structure is
// identical to the best (R12) kernel; each SMSP hosts one warp from EACH group,
// so the two warps' dependency-stall windows decorrelate instead of aligning.
__global__ __launch_bounds__(256, 1) void rec_kernel(float* __restrict__ out)
{
    const int blk = blockIdx.x;
    const int b   = blk >> 6;
    const int h   = (blk >> 1) & 31;
    const int vh  = blk & 1;
    const int hk  = h >> 1;

    const int tid = threadIdx.x;
    const int gid = tid >> 7;          // group 0/1
    const int wt  = tid & 127;
    const int c2  = wt >> 3;           // column pair 0..15 (within group)
    const int p   = wt & 7;            // k-slice 0..7 (16 dims)
    const bool lowp = (p < 4);

    __shared__ float sk[2][2][TB][8][20];    // [group][buf]
    __shared__ float sq[2][2][TB][8][20];
    __shared__ float sv[2][2][TB][32];
    __shared__ float2 sg[2][2][TB];
    __shared__ float2 scr[2][2][TB / 2];

#define GBAR() asm volatile("bar.sync %0, %1;" :: "r"(gid + 1), "n"(128) : "memory")

    ull so[8], sx[8];                  // owned / other column state
#pragma unroll
    for (int i = 0; i < 8; i++) { so[i] = 0ull; sx[i] = 0ull; }

    const float* kbase = g_kn + ((size_t)(b * S_LEN) * HK + hk) * DK;
    const float* qbase = g_qn + ((size_t)(b * S_LEN) * HK + hk) * DK;
    const float* vbase = g_v  + ((size_t)(b * S_LEN) * HV + h) * DV + vh * 64 + gid * 32;
    const float* gbase = g_gate + ((size_t)(b * S_LEN) * HV + h) * 2;
    const size_t qk_stride = (size_t)HK * DK;
    const size_t v_stride  = (size_t)HV * DV;

    auto load_batch = [&](int buf, int t0) {
        // k and q: TB tokens x 32 float4 chunks each (256 each, 2 rounds of 128)
#pragma unroll
        for (int rep = 0; rep < 2; rep++) {
            int i  = wt + rep * 128;
            int tt = i >> 5, j = i & 31;
            cpa16(&sk[gid][buf][tt][j >> 2][(j & 3) * 4],
                  kbase + (size_t)(t0 + tt) * qk_stride + j * 4);
            cpa16(&sq[gid][buf][tt][j >> 2][(j & 3) * 4],
                  qbase + (size_t)(t0 + tt) * qk_stride + j * 4);
        }
        // v: TB tokens x 8 float4 chunks = 64
        if (wt < 64) {
            int tt = wt >> 3, j = wt & 7;
            cpa16(&sv[gid][buf][tt][j * 4],
                  vbase + (size_t)(t0 + tt) * v_stride + j * 4);
        }
        if (wt < TB)
            cpa8(&sg[gid][buf][wt], gbase + (size_t)(t0 + wt) * (HV * 2));
        if (wt < TB / 2)
            cpa8(&scr[gid][buf][wt],
                 &g_cross[(size_t)(b * (S_LEN / 2) + (t0 >> 1) + wt) * HK + hk]);
        cpa_commit();
    };

    load_batch(0, 0);
    cpa_wait0();
    GBAR();
    int buf = 0;

    float* obase = out + ((size_t)(b * S_LEN) * HV + h) * DV + vh * 64 + gid * 32 + c2 * 2;
    const int osel = lowp ? 0 : 1;

    float oo_m = 0.f, oo_o = 0.f;      // prev token's o2 partials (own/other)

    F4U k1A[4], k2A[4], q1A[4], k1B[4], k2B[4], q1B[4];

#define PLOAD(k1r, k2r, q1r, PP) do {                                         \
    const int _s = (PP) * 2;                                                  \
    const float* _k1 = &sk[gid][buf][_s][p][0];                               \
    const float* _k2 = &sk[gid][buf][_s + 1][p][0];                           \
    const float* _q1 = &sq[gid][buf][_s][p][0];                               \
    _Pragma("unroll")                                                         \
    for (int i = 0; i < 4; i++) {                                             \
        k1r[i].f = *reinterpret_cast<const float4*>(_k1 + i * 4);             \
        k2r[i].f = *reinterpret_cast<const float4*>(_k2 + i * 4);             \
        q1r[i].f = *reinterpret_cast<const float4*>(_q1 + i * 4);             \
    }                                                                         \
} while (0)

#define PBODY(k1r, k2r, q1r, PP, T) do {                                      \
    const float2 ga = sg[gid][buf][2 * (PP)];                                 \
    const float2 gb = sg[gid][buf][2 * (PP) + 1];                             \
    const float e1 = ga.x, b1 = ga.y, e2 = gb.x, b2 = gb.y;                   \
    const float2 cr = scr[gid][buf][PP];                                      \
    ull A = 0, B = 0, C = 0, D = 0, E = 0, F = 0;                             \
    _Pragma("unroll")                                                         \
    for (int i = 0; i < 4; i++) {                                             \
        FMA2(A, k1r[i].u[0], so[2*i],   A);                                   \
        FMA2(A, k1r[i].u[1], so[2*i+1], A);                                   \
        FMA2(B, k2r[i].u[0], so[2*i],   B);                                   \
        FMA2(B, k2r[i].u[1], so[2*i+1], B);                                   \
        FMA2(C, q1r[i].u[0], so[2*i],   C);                                   \
        FMA2(C, q1r[i].u[1], so[2*i+1], C);                                   \
        FMA2(D, k1r[i].u[0], sx[2*i],   D);                                   \
        FMA2(D, k1r[i].u[1], sx[2*i+1], D);                                   \
        FMA2(E, k2r[i].u[0], sx[2*i],   E);                                   \
        FMA2(E, k2r[i].u[1], sx[2*i+1], E);                                   \
        FMA2(F, q1r[i].u[0], sx[2*i],   F);                                   \
        FMA2(F, q1r[i].u[1], sx[2*i+1], F);                                   \
    }                                                                         \
    float Pam = sum2(A), Pbm = sum2(B), G1m = sum2(C);                        \
    const float PaO = sum2(D), PbO = sum2(E), G1O = sum2(F);                  \
    Pam  += __shfl_xor_sync(0xffffffffu, PaO,  4);                            \
    Pbm  += __shfl_xor_sync(0xffffffffu, PbO,  4);                            \
    G1m  += __shfl_xor_sync(0xffffffffu, G1O,  4);                            \
    oo_m += __shfl_xor_sync(0xffffffffu, oo_o, 4);                            \
    Pam  += __shfl_xor_sync(0xffffffffu, Pam,  1);                            \
    Pbm  += __shfl_xor_sync(0xffffffffu, Pbm,  1);                            \
    G1m  += __shfl_xor_sync(0xffffffffu, G1m,  1);                            \
    oo_m += __shfl_xor_sync(0xffffffffu, oo_m, 1);                            \
    Pam  += __shfl_xor_sync(0xffffffffu, Pam,  2);                            \
    Pbm  += __shfl_xor_sync(0xffffffffu, Pbm,  2);                            \
    G1m  += __shfl_xor_sync(0xffffffffu, G1m,  2);                            \
    oo_m += __shfl_xor_sync(0xffffffffu, oo_m, 2);                            \
    if ((T) != 0 && (p & 3) == 0)                                             \
        obase[(size_t)((T) - 1) * v_stride + osel] = oo_m;                    \
    const float2 v1f = *reinterpret_cast<const float2*>(&sv[gid][buf][2*(PP)][c2*2]);   \
    const float2 v2f = *reinterpret_cast<const float2*>(&sv[gid][buf][2*(PP)+1][c2*2]); \
    const float v1o = lowp ? v1f.x : v1f.y;                                   \
    const float v2o = lowp ? v2f.x : v2f.y;                                   \
    const float u1 = b1 * (v1o - e1 * Pam);                                   \
    const float k2S1 = e1 * Pbm + cr.x * u1;                                  \
    const float u2 = b2 * (v2o - e2 * k2S1);                                  \
    const float o1 = e1 * G1m + cr.y * u1;                                    \
    if ((p & 3) == 0)                                                         \
        obase[(size_t)(T) * v_stride + osel] = o1;                            \
    const float e12 = e1 * e2;                                                \
    const float c1 = e2 * u1;                                                 \
    const float c1x = __shfl_xor_sync(0xffffffffu, c1, 4);                    \
    const float u2x = __shfl_xor_sync(0xffffffffu, u2, 4);                    \
    const ull ep  = pack2(e12, e12);                                          \
    const ull c1p = pack2(c1, c1), u2p = pack2(u2, u2);                       \
    _Pragma("unroll")                                                         \
    for (int i = 0; i < 4; i++) {        /* owned update overlaps exchange */ \
        MUL2(so[2*i],   so[2*i],   ep);                                       \
        MUL2(so[2*i+1], so[2*i+1], ep);                                       \
        FMA2(so[2*i],   k1r[i].u[0], c1p, so[2*i]);                           \
        FMA2(so[2*i+1], k1r[i].u[1], c1p, so[2*i+1]);                         \
        FMA2(so[2*i],   k2r[i].u[0], u2p, so[2*i]);                           \
        FMA2(so[2*i+1], k2r[i].u[1], u2p, so[2*i+1]);                         \
    }                                                                         \
    const ull c1xp = pack2(c1x, c1x), u2xp = pack2(u2x, u2x);                 \
    _Pragma("unroll")                                                         \
    for (int i = 0; i < 4; i++) {                                             \
        MUL2(sx[2*i],   sx[2*i],   ep);                                       \
        MUL2(sx[2*i+1], sx[2*i+1], ep);                                       \
        FMA2(sx[2*i],   k1r[i].u[0], c1xp, sx[2*i]);                          \
        FMA2(sx[2*i+1], k1r[i].u[1], c1xp, sx[2*i+1]);                        \
        FMA2(sx[2*i],   k2r[i].u[0], u2xp, sx[2*i]);                          \
        FMA2(sx[2*i+1], k2r[i].u[1], u2xp, sx[2*i+1]);                        \
    }                                                                         \
    F4U q2r[4];                                                               \
    const float* _q2 = &sq[gid][buf][2*(PP)+1][p][0];                         \
    _Pragma("unroll")                                                         \
    for (int i = 0; i < 4; i++)                                               \
        q2r[i].f = *reinterpret_cast<const float4*>(_q2 + i * 4);             \
    ull qa0 = 0, qa1 = 0, qb0 = 0, qb1 = 0;                                   \
    _Pragma("unroll")                                                         \
    for (int i = 0; i < 4; i++) {                                             \
        FMA2(qa0, q2r[i].u[0], so[2*i],   qa0);                               \
        FMA2(qa1, q2r[i].u[1], so[2*i+1], qa1);                               \
        FMA2(qb0, q2r[i].u[0], sx[2*i],   qb0);                               \
        FMA2(qb1, q2r[i].u[1], sx[2*i+1], qb1);                               \
    }                                                                         \
    ADD2(qa0, qa0, qa1); ADD2(qb0, qb0, qb1);                                 \
    float2 gqa = unpack2(qa0), gqb = unpack2(qb0);                            \
    oo_m = gqa.x + gqa.y;                                                     \
    oo_o = gqb.x + gqb.y;                                                     \
} while (0)

#pragma unroll 1
    for (int t0 = 0; t0 < S_LEN; t0 += TB) {
        if (t0 + TB < S_LEN) load_batch(buf ^ 1, t0 + TB);

        PLOAD(k1A, k2A, q1A, 0);
#pragma unroll 2
        for (int pp = 0; pp < TB / 2; pp += 2) {
            PLOAD(k1B, k2B, q1B, pp + 1);
            PBODY(k1A, k2A, q1A, pp, t0 + 2 * pp);
            {
                int pn = pp + 2; if (pn > TB / 2 - 1) pn = TB / 2 - 1;
                PLOAD(k1A, k2A, q1A, pn);
            }
            PBODY(k1B, k2B, q1B, pp + 1, t0 + 2 * (pp + 1));
        }

        cpa_wait0();
        GBAR();
        buf ^= 1;
    }

    // drain: reduce and store the final token's o2
    {
        oo_m += __shfl_xor_sync(0xffffffffu, oo_o, 4);
        oo_m += __shfl_xor_sync(0xffffffffu, oo_m, 1);
        oo_m += __shfl_xor_sync(0xffffffffu, oo_m, 2);
        if ((p & 3) == 0)
            obase[(size_t)(S_LEN - 1) * v_stride + osel] = oo_m;
    }
#undef PLOAD
#undef PBODY
#undef GBAR
}

// ---------------- launch ----------------
extern "C" void kernel_launch(void* const* d_in, const int* in_sizes, int n_in,
                              void* d_out, int out_size)
{
    const float* mixed_qkv = (const float*)d_in[0];
    const float* bvec      = (const float*)d_in[1];
    const float* avec      = (const float*)d_in[2];
    const float* convw     = (const float*)d_in[3];
    const float* dt_bias   = (const float*)d_in[4];
    const float* alog      = (const float*)d_in[5];
    float* out = (float*)d_out;

    prep_kernel<<<2048, 256>>>(mixed_qkv, convw);
    cross_kernel<<<BQ * HK * (S_LEN / 2) / 8, 256>>>();
    gate_kernel<<<NROWS * HV / 256, 256>>>(bvec, avec, dt_bias, alog);
    rec_kernel<<<BQ * HV * 2, 256>>>(out);
}